// round 14
// baseline (speedup 1.0000x reference)
#include <cuda_runtime.h>
#include <cuda_bf16.h>

#define NN   4096
#define TT   48
#define HH   64
#define C4   256
#define MAXW 128
#define ROWS 28
#define GRID 147

#define SUP0 152      // su pitch (bf16) cell0: K=144 + 8 pad
#define NKT0 9        // 144/16
#define SUP1 264      // su pitch (bf16) cell1: K=256 + 8 pad
#define NKT1 16
#define CWP  260      // comb pitch (fp32)

// ---------------- device scratch (no allocations allowed) ----------------
__device__ __align__(16) float g_dinv[NN];
__device__ __align__(16) int2  g_cv[NN * MAXW];    // (col, __float_as_int(val))
__device__ __align__(16) int   g_len[NN];
__device__ __align__(16) float g_AX[TT * NN * 2];
__device__ __align__(16) __nv_bfloat16 g_Wp0[144 * C4];  // fragment-packed [gcWh0;liWh0;Wx;0]
__device__ __align__(16) __nv_bfloat16 g_Wp1[256 * C4];  // fragment-packed [gcWi1;liWi1;gcWh1;liWh1]
__device__ __align__(16) float g_b0[C4];
__device__ __align__(16) float g_b1[C4];
__device__ __align__(16) float g_c0[2][NN * HH];
__device__ __align__(16) float g_c1[2][NN * HH];
__device__ __align__(16) __nv_bfloat16 g_bh0[2][NN * HH];  // bf16 h mirrors
__device__ __align__(16) __nv_bfloat16 g_bh1[2][NN * HH];

// ---------------- helpers ----------------
__device__ __forceinline__ float sigf(float v)  { return 1.f / (1.f + __expf(-v)); }
__device__ __forceinline__ float tanhf2(float v){ return 2.f / (1.f + __expf(-2.f * v)) - 1.f; }

__device__ __forceinline__ void gacc(float4& a, float v, const __nv_bfloat16* bh, int c, int lane) {
    uint2 raw = *((const uint2*)(bh + (size_t)c * HH) + lane);
    __nv_bfloat162 b01 = *(__nv_bfloat162*)&raw.x;
    __nv_bfloat162 b23 = *(__nv_bfloat162*)&raw.y;
    float2 f01 = __bfloat1622float2(b01), f23 = __bfloat1622float2(b23);
    a.x += v * f01.x; a.y += v * f01.y; a.z += v * f23.x; a.w += v * f23.y;
}

__device__ __forceinline__ uint2 f4_to_b4(float4 a) {
    __nv_bfloat162 lo = __floats2bfloat162_rn(a.x, a.y);
    __nv_bfloat162 hi = __floats2bfloat162_rn(a.z, a.w);
    uint2 r; r.x = *(unsigned*)&lo; r.y = *(unsigned*)&hi; return r;
}

__device__ __forceinline__ void mma_bf16(float* c, unsigned a0, unsigned a1, unsigned a2, unsigned a3,
                                         unsigned b0, unsigned b1) {
    asm volatile("mma.sync.aligned.m16n8k16.row.col.f32.bf16.bf16.f32 "
                 "{%0,%1,%2,%3},{%4,%5,%6,%7},{%8,%9},{%0,%1,%2,%3};"
                 : "+f"(c[0]), "+f"(c[1]), "+f"(c[2]), "+f"(c[3])
                 : "r"(a0), "r"(a1), "r"(a2), "r"(a3), "r"(b0), "r"(b1));
}

__host__ __device__ __forceinline__ int fragoff(int k, int n, int nkt) {
    int kt = k >> 4, kr = k & 15, nt = n >> 3, nr = n & 7;
    int t = nr * 4 + ((kr & 7) >> 1);
    int pos = t * 4 + ((kr >> 3) << 1) + (kr & 1);
    return ((nt * nkt + kt) << 7) + pos;
}

// ---------------- setup kernels ----------------
__global__ void k_dinv(const float* __restrict__ adj) {
    int row  = blockIdx.x * 8 + (threadIdx.x >> 5);
    int lane = threadIdx.x & 31;
    if (row >= NN) return;
    float s = 0.f;
    for (int j = lane; j < NN; j += 32) s += adj[(size_t)row * NN + j];
    #pragma unroll
    for (int o = 16; o; o >>= 1) s += __shfl_xor_sync(0xffffffffu, s, o);
    if (lane == 0) g_dinv[row] = rsqrtf(s + 1.f);   // A = adj + I
}

__global__ void k_build(const float* __restrict__ adj) {
    int row  = blockIdx.x * 8 + (threadIdx.x >> 5);
    int lane = threadIdx.x & 31;
    if (row >= NN) return;
    float dr = g_dinv[row];
    int base = 0;
    for (int j0 = 0; j0 < NN; j0 += 32) {
        int   j    = j0 + lane;
        float v    = adj[(size_t)row * NN + j];
        bool  pres = (v != 0.f) || (j == row);
        float aval = v + ((j == row) ? 1.f : 0.f);
        unsigned m = __ballot_sync(0xffffffffu, pres);
        if (pres) {
            int pos = base + __popc(m & ((1u << lane) - 1u));
            if (pos < MAXW)
                g_cv[row * MAXW + pos] = make_int2(j, __float_as_int(aval * dr * g_dinv[j]));
        }
        base += __popc(m);
    }
    if (base > MAXW) base = MAXW;
    if (lane == 0) g_len[row] = base;
}

__global__ void k_prep(const float* __restrict__ x,
                       const float* gcWi0, const float* gcWh0, const float* liWi0, const float* liWh0,
                       const float* gcWi1, const float* liWi1, const float* gcWh1, const float* liWh1,
                       const float* bi0, const float* bh0, const float* lbi0, const float* lbh0,
                       const float* bi1, const float* bh1, const float* lbi1, const float* lbh1) {
    int idx = blockIdx.x * blockDim.x + threadIdx.x;
    const int W0E = 144 * C4, W1E = 256 * C4;
    int o = idx;
    if (o < W0E) {
        int k = o >> 8, n = o & 255;
        float v;
        if (k < 64)       v = gcWh0[k * C4 + n];
        else if (k < 128) v = liWh0[(k - 64) * C4 + n];
        else {
            int q = k - 128;
            v = (q < 2) ? gcWi0[q * C4 + n] : (q < 4) ? liWi0[(q - 2) * C4 + n] : 0.f;
        }
        g_Wp0[fragoff(k, n, NKT0)] = __float2bfloat16(v);
        return;
    }
    o -= W0E;
    if (o < W1E) {
        int k = o >> 8, n = o & 255;
        int seg = k >> 6, rr = k & 63;
        const float* s = (seg == 0) ? gcWi1 : (seg == 1) ? liWi1 : (seg == 2) ? gcWh1 : liWh1;
        g_Wp1[fragoff(k, n, NKT1)] = __float2bfloat16(s[rr * C4 + n]);
        return;
    }
    o -= W1E;
    if (o < C4) { g_b0[o] = bi0[o] + bh0[o] + lbi0[o] + lbh0[o]; return; }
    o -= C4;
    if (o < C4) { g_b1[o] = bi1[o] + bh1[o] + lbi1[o] + lbh1[o]; return; }
    o -= C4;
    if (o < NN * HH) {
        g_c0[0][o] = 0.f; g_c1[0][o] = 0.f;
        g_bh0[0][o] = __float2bfloat16(0.f);
        g_bh1[0][o] = __float2bfloat16(0.f);
        return;
    }
    o -= NN * HH;
    if (o < TT * NN) {
        int t = o / NN, i = o - t * NN;
        int len = g_len[i];
        const int2* cp = g_cv + (size_t)i * MAXW;
        float a0 = 0.f, a1 = 0.f;
        for (int k = 0; k < len; k++) {
            int2 cv = cp[k];
            float v = __int_as_float(cv.y);
            float2 xv = *(const float2*)&x[(size_t)t * (NN * 2) + cv.x * 2];
            a0 += v * xv.x; a1 += v * xv.y;
        }
        *(float2*)&g_AX[((size_t)t * NN + i) * 2] = make_float2(a0, a1);
    }
}
#define PREP_TOTAL (144 * C4 + 256 * C4 + 2 * C4 + NN * HH + TT * NN)

// ================= initial cell 0 (t = 0 only) =================
#define NTHR0 512
#define C0_SMEM (32 * SUP0 * 2 + 32 * CWP * 4)

__global__ __launch_bounds__(NTHR0) void k_cell0(const float* __restrict__ x, int t, int pin, int pout) {
    extern __shared__ __align__(16) char smem[];
    __nv_bfloat16* su = (__nv_bfloat16*)smem;
    float* cw = (float*)(smem + 32 * SUP0 * 2);

    const int tid  = threadIdx.x;
    const int row0 = blockIdx.x * ROWS;
    const __nv_bfloat16* __restrict__ bin = g_bh0[pin];

    {
        uint4* p = (uint4*)su;
        for (int i = tid; i < 32 * SUP0 / 8; i += NTHR0) p[i] = make_uint4(0, 0, 0, 0);
    }
    __syncthreads();

    if (tid < 448) {
        int r = tid >> 4, lane = tid & 15;
        int grow = min(row0 + r, NN - 1);
        uint2 v0 = *((const uint2*)(bin + (size_t)grow * HH) + lane);
        *(uint2*)&su[r * SUP0 + 64 + lane * 4] = v0;
    }
    if (tid < ROWS) {
        int grow = min(row0 + tid, NN - 1);
        float2 axv = *(const float2*)&g_AX[((size_t)t * NN + grow) * 2];
        float2 xv  = *(const float2*)&x[(size_t)t * (NN * 2) + grow * 2];
        *(uint2*)&su[tid * SUP0 + 128] = f4_to_b4(make_float4(axv.x, axv.y, xv.x, xv.y));
    }
    if (tid < 448) {
        int r = tid >> 4, lane = tid & 15;
        int grow = min(row0 + r, NN - 1);
        int len = g_len[grow];
        const int2* cb = g_cv + (size_t)grow * MAXW;
        float4 a4 = make_float4(0.f, 0.f, 0.f, 0.f);
        #pragma unroll 4
        for (int k = 0; k < len; k++) {
            int2 cv = __ldg(&cb[k]);
            gacc(a4, __int_as_float(cv.y), bin, cv.x, lane);
        }
        *(uint2*)&su[r * SUP0 + lane * 4] = f4_to_b4(a4);
    }
    __syncthreads();

    {
        const int w = tid >> 5, tl = tid & 31;
        const int mt = w & 1, nc = w >> 1;
        const int rA = mt * 16 + (tl >> 2);
        const int cA = 2 * (tl & 3);
        float c[4][4];
        #pragma unroll
        for (int j = 0; j < 4; j++) { c[j][0] = c[j][1] = c[j][2] = c[j][3] = 0.f; }
        #pragma unroll 1
        for (int kt = 0; kt < NKT0; kt++) {
            unsigned a0 = *(const unsigned*)&su[rA * SUP0 + kt * 16 + cA];
            unsigned a1 = *(const unsigned*)&su[(rA + 8) * SUP0 + kt * 16 + cA];
            unsigned a2 = *(const unsigned*)&su[rA * SUP0 + kt * 16 + cA + 8];
            unsigned a3 = *(const unsigned*)&su[(rA + 8) * SUP0 + kt * 16 + cA + 8];
            #pragma unroll
            for (int j = 0; j < 4; j++) {
                int nt = nc * 4 + j;
                uint2 b = __ldg((const uint2*)g_Wp0 + (nt * NKT0 + kt) * 32 + tl);
                mma_bf16(c[j], a0, a1, a2, a3, b.x, b.y);
            }
        }
        int r = mt * 16 + (tl >> 2);
        #pragma unroll
        for (int j = 0; j < 4; j++) {
            int n = nc * 32 + j * 8 + 2 * (tl & 3);
            float2 bb = *(const float2*)&g_b0[n];
            cw[r * CWP + n]           = c[j][0] + bb.x;
            cw[r * CWP + n + 1]       = c[j][1] + bb.y;
            cw[(r + 8) * CWP + n]     = c[j][2] + bb.x;
            cw[(r + 8) * CWP + n + 1] = c[j][3] + bb.y;
        }
    }
    __syncthreads();

    const float* __restrict__ cold = g_c0[pin];
    float* __restrict__ cn = g_c0[pout];
    __nv_bfloat16* __restrict__ bo = g_bh0[pout];
    for (int i = tid; i < ROWS * HH; i += NTHR0) {
        int r = i >> 6, h = i & 63;
        int grow = row0 + r;
        if (grow < NN) {
            float ig = cw[r * CWP + h],       fg = cw[r * CWP + 64 + h];
            float og = cw[r * CWP + 128 + h], gg = cw[r * CWP + 192 + h];
            size_t gi = (size_t)grow * HH + h;
            float cvv = sigf(fg) * cold[gi] + sigf(ig) * tanhf2(gg);
            cn[gi] = cvv;
            bo[gi] = __float2bfloat16(sigf(og) * tanhf2(cvv));
        }
    }
}

// ================= fused step: cell1(t) + cell0(t+1) =================
// smem: su1 bf16[32][SUP1] | su0 bf16[32][SUP0] | cw1 f32[32][CWP] | cw0 f32[32][CWP]
#define O_SU0 (32 * SUP1 * 2)
#define O_CW1 (O_SU0 + 32 * SUP0 * 2)
#define O_CW0 (O_CW1 + 32 * CWP * 4)
#define STEP_SMEM (O_CW0 + 32 * CWP * 4)

__global__ __launch_bounds__(1024) void k_step(const float* __restrict__ x,
                                               const float* __restrict__ outW,
                                               const float* __restrict__ outb,
                                               float* __restrict__ out, int t) {
    extern __shared__ __align__(16) char smem[];
    __nv_bfloat16* su1 = (__nv_bfloat16*)smem;
    __nv_bfloat16* su0 = (__nv_bfloat16*)(smem + O_SU0);
    float* cw1 = (float*)(smem + O_CW1);
    float* cw0 = (float*)(smem + O_CW0);
    float* hl  = (float*)(smem + O_SU0);      // aliases su0 (last step only)

    const int tid  = threadIdx.x;
    const int row0 = blockIdx.x * ROWS;
    const int pin = t & 1, pout = pin ^ 1;
    const bool last = (t == TT - 1);
    const __nv_bfloat16* __restrict__ bh0n = g_bh0[pout];   // new h0 (from prev launch)
    const __nv_bfloat16* __restrict__ bh1o = g_bh1[pin];    // old h1

    // zero su1 + su0
    {
        uint4* p = (uint4*)smem;
        for (int i = tid; i < (32 * SUP1 + 32 * SUP0) / 8; i += 1024) p[i] = make_uint4(0, 0, 0, 0);
    }
    __syncthreads();

    // direct operands
    if (tid < 448) {
        int r = tid >> 4, lane = tid & 15;
        int grow = min(row0 + r, NN - 1);
        uint2 v0 = *((const uint2*)(bh0n + (size_t)grow * HH) + lane);
        uint2 v1 = *((const uint2*)(bh1o + (size_t)grow * HH) + lane);
        *(uint2*)&su1[r * SUP1 + 64 + lane * 4]  = v0;
        *(uint2*)&su1[r * SUP1 + 192 + lane * 4] = v1;
        *(uint2*)&su0[r * SUP0 + 64 + lane * 4]  = v0;
    }
    if (tid < ROWS && !last) {
        int grow = min(row0 + tid, NN - 1);
        float2 axv = *(const float2*)&g_AX[((size_t)(t + 1) * NN + grow) * 2];
        float2 xv  = *(const float2*)&x[(size_t)(t + 1) * (NN * 2) + grow * 2];
        *(uint2*)&su0[tid * SUP0 + 128] = f4_to_b4(make_float4(axv.x, axv.y, xv.x, xv.y));
    }

    // early B-fragment prefetch (all warps; rides out the gather + barrier)
    const int w = tid >> 5, tl = tid & 31;
    const int mt = w & 1, nq = w >> 1;
    const uint2* p1 = (const uint2*)g_Wp1 + (nq * 2 * NKT1) * 32 + tl;   // n-tiles 2nq, 2nq+1
    const uint2* p0 = (const uint2*)g_Wp0 + (nq * 2 * NKT0) * 32 + tl;
    uint2 b1a = __ldg(p1), b1b = __ldg(p1 + NKT1 * 32);
    uint2 b0a = make_uint2(0, 0), b0b = make_uint2(0, 0);
    if (!last) { b0a = __ldg(p0); b0b = __ldg(p0 + NKT0 * 32); }

    // shared gather, batch-of-4 index prefetch for MLP
    if (tid < 896) {
        int r = tid >> 5, half = (tid >> 4) & 1, lane = tid & 15;
        int grow = min(row0 + r, NN - 1);
        int len = g_len[grow];
        const int2* cb = g_cv + (size_t)grow * MAXW;
        float4 a0 = make_float4(0.f, 0.f, 0.f, 0.f);
        float4 a1 = make_float4(0.f, 0.f, 0.f, 0.f);
        int k = half;
        for (; k + 6 < len; k += 8) {
            int2 v0 = __ldg(&cb[k]);
            int2 v1 = __ldg(&cb[k + 2]);
            int2 v2 = __ldg(&cb[k + 4]);
            int2 v3 = __ldg(&cb[k + 6]);
            float f0 = __int_as_float(v0.y), f1 = __int_as_float(v1.y);
            float f2 = __int_as_float(v2.y), f3 = __int_as_float(v3.y);
            gacc(a0, f0, bh0n, v0.x, lane); gacc(a1, f0, bh1o, v0.x, lane);
            gacc(a0, f1, bh0n, v1.x, lane); gacc(a1, f1, bh1o, v1.x, lane);
            gacc(a0, f2, bh0n, v2.x, lane); gacc(a1, f2, bh1o, v2.x, lane);
            gacc(a0, f3, bh0n, v3.x, lane); gacc(a1, f3, bh1o, v3.x, lane);
        }
        for (; k < len; k += 2) {
            int2 v = __ldg(&cb[k]);
            float f = __int_as_float(v.y);
            gacc(a0, f, bh0n, v.x, lane); gacc(a1, f, bh1o, v.x, lane);
        }
        a0.x += __shfl_xor_sync(0xffffffffu, a0.x, 16);
        a0.y += __shfl_xor_sync(0xffffffffu, a0.y, 16);
        a0.z += __shfl_xor_sync(0xffffffffu, a0.z, 16);
        a0.w += __shfl_xor_sync(0xffffffffu, a0.w, 16);
        a1.x += __shfl_xor_sync(0xffffffffu, a1.x, 16);
        a1.y += __shfl_xor_sync(0xffffffffu, a1.y, 16);
        a1.z += __shfl_xor_sync(0xffffffffu, a1.z, 16);
        a1.w += __shfl_xor_sync(0xffffffffu, a1.w, 16);
        if (half == 0) {
            uint2 q0 = f4_to_b4(a0), q1 = f4_to_b4(a1);
            *(uint2*)&su1[r * SUP1 + lane * 4]       = q0;
            *(uint2*)&su0[r * SUP0 + lane * 4]       = q0;
            *(uint2*)&su1[r * SUP1 + 128 + lane * 4] = q1;
        }
    }
    __syncthreads();

    // merged MMA: cell1 (16 kt) with cell0 (9 kt) interleaved, both streams prefetched
    const int rA = mt * 16 + (tl >> 2), cA = 2 * (tl & 3);
    float c1r[2][4], c0r[2][4];
    #pragma unroll
    for (int j = 0; j < 2; j++)
        #pragma unroll
        for (int q = 0; q < 4; q++) { c1r[j][q] = 0.f; c0r[j][q] = 0.f; }
    #pragma unroll 1
    for (int kt = 0; kt < NKT1; kt++) {
        uint2 n1a = make_uint2(0, 0), n1b = n1a, n0a = n1a, n0b = n1a;
        if (kt + 1 < NKT1) {
            n1a = __ldg(p1 + (kt + 1) * 32);
            n1b = __ldg(p1 + (NKT1 + kt + 1) * 32);
        }
        if (!last && kt + 1 < NKT0) {
            n0a = __ldg(p0 + (kt + 1) * 32);
            n0b = __ldg(p0 + (NKT0 + kt + 1) * 32);
        }
        unsigned a0 = *(const unsigned*)&su1[rA * SUP1 + kt * 16 + cA];
        unsigned a1 = *(const unsigned*)&su1[(rA + 8) * SUP1 + kt * 16 + cA];
        unsigned a2 = *(const unsigned*)&su1[rA * SUP1 + kt * 16 + cA + 8];
        unsigned a3 = *(const unsigned*)&su1[(rA + 8) * SUP1 + kt * 16 + cA + 8];
        mma_bf16(c1r[0], a0, a1, a2, a3, b1a.x, b1a.y);
        mma_bf16(c1r[1], a0, a1, a2, a3, b1b.x, b1b.y);
        if (!last && kt < NKT0) {
            unsigned d0 = *(const unsigned*)&su0[rA * SUP0 + kt * 16 + cA];
            unsigned d1 = *(const unsigned*)&su0[(rA + 8) * SUP0 + kt * 16 + cA];
            unsigned d2 = *(const unsigned*)&su0[rA * SUP0 + kt * 16 + cA + 8];
            unsigned d3 = *(const unsigned*)&su0[(rA + 8) * SUP0 + kt * 16 + cA + 8];
            mma_bf16(c0r[0], d0, d1, d2, d3, b0a.x, b0a.y);
            mma_bf16(c0r[1], d0, d1, d2, d3, b0b.x, b0b.y);
        }
        b1a = n1a; b1b = n1b; b0a = n0a; b0b = n0b;
    }
    {   // write combs (+bias)
        int r = mt * 16 + (tl >> 2);
        #pragma unroll
        for (int j = 0; j < 2; j++) {
            int n = nq * 16 + j * 8 + 2 * (tl & 3);
            float2 bb1 = *(const float2*)&g_b1[n];
            cw1[r * CWP + n]           = c1r[j][0] + bb1.x;
            cw1[r * CWP + n + 1]       = c1r[j][1] + bb1.y;
            cw1[(r + 8) * CWP + n]     = c1r[j][2] + bb1.x;
            cw1[(r + 8) * CWP + n + 1] = c1r[j][3] + bb1.y;
            if (!last) {
                float2 bb0 = *(const float2*)&g_b0[n];
                cw0[r * CWP + n]           = c0r[j][0] + bb0.x;
                cw0[r * CWP + n + 1]       = c0r[j][1] + bb0.y;
                cw0[(r + 8) * CWP + n]     = c0r[j][2] + bb0.x;
                cw0[(r + 8) * CWP + n + 1] = c0r[j][3] + bb0.y;
            }
        }
    }
    __syncthreads();

    // epilogue cell1(t)
    {
        const float* __restrict__ cold = g_c1[pin];
        float* __restrict__ cn = g_c1[pout];
        __nv_bfloat16* __restrict__ bo = g_bh1[pout];
        #pragma unroll
        for (int it = 0; it < 2; it++) {
            int i = tid + it * 1024;
            if (i < ROWS * HH) {
                int r = i >> 6, h = i & 63;
                int grow = row0 + r;
                if (grow < NN) {
                    float ig = cw1[r * CWP + h],       fg = cw1[r * CWP + 64 + h];
                    float og = cw1[r * CWP + 128 + h], gg = cw1[r * CWP + 192 + h];
                    size_t gi = (size_t)grow * HH + h;
                    float cvv = sigf(fg) * cold[gi] + sigf(ig) * tanhf2(gg);
                    cn[gi] = cvv;
                    float hv = sigf(og) * tanhf2(cvv);
                    bo[gi] = __float2bfloat16(hv);
                    if (last) hl[r * 64 + h] = hv;
                }
            }
        }
    }
    if (!last) {
        // epilogue cell0(t+1): pin' = pout, pout' = pin
        const float* __restrict__ cold = g_c0[pout];
        float* __restrict__ cn = g_c0[pin];
        __nv_bfloat16* __restrict__ bo = g_bh0[pin];
        #pragma unroll
        for (int it = 0; it < 2; it++) {
            int i = tid + it * 1024;
            if (i < ROWS * HH) {
                int r = i >> 6, h = i & 63;
                int grow = row0 + r;
                if (grow < NN) {
                    float ig = cw0[r * CWP + h],       fg = cw0[r * CWP + 64 + h];
                    float og = cw0[r * CWP + 128 + h], gg = cw0[r * CWP + 192 + h];
                    size_t gi = (size_t)grow * HH + h;
                    float cvv = sigf(fg) * cold[gi] + sigf(ig) * tanhf2(gg);
                    cn[gi] = cvv;
                    bo[gi] = __float2bfloat16(sigf(og) * tanhf2(cvv));
                }
            }
        }
    } else {
        // output projection from fp32 h1 in smem
        __syncthreads();
        if (tid < ROWS * 12) {
            int r = tid / 12, p = tid - r * 12;
            int grow = row0 + r;
            if (grow < NN) {
                float s = outb[p];
                #pragma unroll
                for (int k = 0; k < HH; k++) s += hl[r * 64 + k] * outW[k * 12 + p];
                out[grow * 12 + p] = s;
            }
        }
    }
}

extern "C" void kernel_launch(void* const* d_in, const int* in_sizes, int n_in,
                              void* d_out, int out_size) {
    const float* x     = (const float*)d_in[0];
    const float* adj   = (const float*)d_in[1];
    const float* gcWi0 = (const float*)d_in[2];
    const float* gcbi0 = (const float*)d_in[3];
    const float* gcWh0 = (const float*)d_in[4];
    const float* gcbh0 = (const float*)d_in[5];
    const float* liWi0 = (const float*)d_in[6];
    const float* libi0 = (const float*)d_in[7];
    const float* liWh0 = (const float*)d_in[8];
    const float* libh0 = (const float*)d_in[9];
    const float* gcWi1 = (const float*)d_in[10];
    const float* gcbi1 = (const float*)d_in[11];
    const float* gcWh1 = (const float*)d_in[12];
    const float* gcbh1 = (const float*)d_in[13];
    const float* liWi1 = (const float*)d_in[14];
    const float* libi1 = (const float*)d_in[15];
    const float* liWh1 = (const float*)d_in[16];
    const float* libh1 = (const float*)d_in[17];
    const float* outW  = (const float*)d_in[18];
    const float* outb  = (const float*)d_in[19];
    float* out = (float*)d_out;

    cudaFuncSetAttribute(k_cell0, cudaFuncAttributeMaxDynamicSharedMemorySize, C0_SMEM);
    cudaFuncSetAttribute(k_step, cudaFuncAttributeMaxDynamicSharedMemorySize, STEP_SMEM);

    k_dinv<<<NN / 8, 256>>>(adj);
    k_build<<<NN / 8, 256>>>(adj);
    k_prep<<<(PREP_TOTAL + 255) / 256, 256>>>(x,
        gcWi0, gcWh0, liWi0, liWh0, gcWi1, liWi1, gcWh1, liWh1,
        gcbi0, gcbh0, libi0, libh0, gcbi1, gcbh1, libi1, libh1);

    k_cell0<<<GRID, NTHR0, C0_SMEM>>>(x, 0, 0, 1);           // cell0 of step 0
    for (int t = 0; t < TT; t++)
        k_step<<<GRID, 1024, STEP_SMEM>>>(x, outW, outb, out, t);  // cell1(t) + cell0(t+1)
}

// round 15
// speedup vs baseline: 1.0262x; 1.0262x over previous
#include <cuda_runtime.h>
#include <cuda_bf16.h>

#define NN   4096
#define TT   48
#define HH   64
#define C4   256
#define MAXW 128
#define ROWS 28
#define GRID 147

#define SUP0 152      // su pitch (bf16) cell0: K=144 + 8 pad
#define NKT0 9        // 144/16
#define SUP1 264      // su pitch (bf16) cell1: K=256 + 8 pad
#define NKT1 16
#define CWP  260      // comb pitch (fp32)

// ---------------- device scratch (no allocations allowed) ----------------
__device__ __align__(16) float g_dinv[NN];
__device__ __align__(16) int2  g_cv[NN * MAXW];    // (col, __float_as_int(val))
__device__ __align__(16) int   g_len[NN];
__device__ __align__(16) float g_AX[TT * NN * 2];
__device__ __align__(16) __nv_bfloat16 g_Wp0[144 * C4];  // fragment-packed [gcWh0;liWh0;Wx;0]
__device__ __align__(16) __nv_bfloat16 g_Wp1[256 * C4];  // fragment-packed [gcWi1;liWi1;gcWh1;liWh1]
__device__ __align__(16) float g_b0[C4];
__device__ __align__(16) float g_b1[C4];
__device__ __align__(16) float g_c0[2][NN * HH];
__device__ __align__(16) float g_c1[2][NN * HH];
__device__ __align__(16) __nv_bfloat16 g_bh0[2][NN * HH];  // bf16 h mirrors
__device__ __align__(16) __nv_bfloat16 g_bh1[2][NN * HH];

// ---------------- helpers ----------------
__device__ __forceinline__ float sigf(float v)  { return 1.f / (1.f + __expf(-v)); }
__device__ __forceinline__ float tanhf2(float v){ return 2.f / (1.f + __expf(-2.f * v)) - 1.f; }

__device__ __forceinline__ void gacc(float4& a, float v, const __nv_bfloat16* bh, int c, int lane) {
    uint2 raw = *((const uint2*)(bh + (size_t)c * HH) + lane);
    __nv_bfloat162 b01 = *(__nv_bfloat162*)&raw.x;
    __nv_bfloat162 b23 = *(__nv_bfloat162*)&raw.y;
    float2 f01 = __bfloat1622float2(b01), f23 = __bfloat1622float2(b23);
    a.x += v * f01.x; a.y += v * f01.y; a.z += v * f23.x; a.w += v * f23.y;
}

__device__ __forceinline__ uint2 f4_to_b4(float4 a) {
    __nv_bfloat162 lo = __floats2bfloat162_rn(a.x, a.y);
    __nv_bfloat162 hi = __floats2bfloat162_rn(a.z, a.w);
    uint2 r; r.x = *(unsigned*)&lo; r.y = *(unsigned*)&hi; return r;
}

__device__ __forceinline__ void mma_bf16(float* c, unsigned a0, unsigned a1, unsigned a2, unsigned a3,
                                         unsigned b0, unsigned b1) {
    asm volatile("mma.sync.aligned.m16n8k16.row.col.f32.bf16.bf16.f32 "
                 "{%0,%1,%2,%3},{%4,%5,%6,%7},{%8,%9},{%0,%1,%2,%3};"
                 : "+f"(c[0]), "+f"(c[1]), "+f"(c[2]), "+f"(c[3])
                 : "r"(a0), "r"(a1), "r"(a2), "r"(a3), "r"(b0), "r"(b1));
}

__host__ __device__ __forceinline__ int fragoff(int k, int n, int nkt) {
    int kt = k >> 4, kr = k & 15, nt = n >> 3, nr = n & 7;
    int t = nr * 4 + ((kr & 7) >> 1);
    int pos = t * 4 + ((kr >> 3) << 1) + (kr & 1);
    return ((nt * nkt + kt) << 7) + pos;
}

// ---------------- setup kernels ----------------
__global__ void k_dinv(const float* __restrict__ adj) {
    int row  = blockIdx.x * 8 + (threadIdx.x >> 5);
    int lane = threadIdx.x & 31;
    if (row >= NN) return;
    float s = 0.f;
    for (int j = lane; j < NN; j += 32) s += adj[(size_t)row * NN + j];
    #pragma unroll
    for (int o = 16; o; o >>= 1) s += __shfl_xor_sync(0xffffffffu, s, o);
    if (lane == 0) g_dinv[row] = rsqrtf(s + 1.f);   // A = adj + I
}

__global__ void k_build(const float* __restrict__ adj) {
    int row  = blockIdx.x * 8 + (threadIdx.x >> 5);
    int lane = threadIdx.x & 31;
    if (row >= NN) return;
    float dr = g_dinv[row];
    int base = 0;
    for (int j0 = 0; j0 < NN; j0 += 32) {
        int   j    = j0 + lane;
        float v    = adj[(size_t)row * NN + j];
        bool  pres = (v != 0.f) || (j == row);
        float aval = v + ((j == row) ? 1.f : 0.f);
        unsigned m = __ballot_sync(0xffffffffu, pres);
        if (pres) {
            int pos = base + __popc(m & ((1u << lane) - 1u));
            if (pos < MAXW)
                g_cv[row * MAXW + pos] = make_int2(j, __float_as_int(aval * dr * g_dinv[j]));
        }
        base += __popc(m);
    }
    if (base > MAXW) base = MAXW;
    if (lane == 0) g_len[row] = base;
}

__global__ void k_prep(const float* __restrict__ x,
                       const float* gcWi0, const float* gcWh0, const float* liWi0, const float* liWh0,
                       const float* gcWi1, const float* liWi1, const float* gcWh1, const float* liWh1,
                       const float* bi0, const float* bh0, const float* lbi0, const float* lbh0,
                       const float* bi1, const float* bh1, const float* lbi1, const float* lbh1) {
    int idx = blockIdx.x * blockDim.x + threadIdx.x;
    const int W0E = 144 * C4, W1E = 256 * C4;
    int o = idx;
    if (o < W0E) {
        int k = o >> 8, n = o & 255;
        float v;
        if (k < 64)       v = gcWh0[k * C4 + n];
        else if (k < 128) v = liWh0[(k - 64) * C4 + n];
        else {
            int q = k - 128;
            v = (q < 2) ? gcWi0[q * C4 + n] : (q < 4) ? liWi0[(q - 2) * C4 + n] : 0.f;
        }
        g_Wp0[fragoff(k, n, NKT0)] = __float2bfloat16(v);
        return;
    }
    o -= W0E;
    if (o < W1E) {
        int k = o >> 8, n = o & 255;
        int seg = k >> 6, rr = k & 63;
        const float* s = (seg == 0) ? gcWi1 : (seg == 1) ? liWi1 : (seg == 2) ? gcWh1 : liWh1;
        g_Wp1[fragoff(k, n, NKT1)] = __float2bfloat16(s[rr * C4 + n]);
        return;
    }
    o -= W1E;
    if (o < C4) { g_b0[o] = bi0[o] + bh0[o] + lbi0[o] + lbh0[o]; return; }
    o -= C4;
    if (o < C4) { g_b1[o] = bi1[o] + bh1[o] + lbi1[o] + lbh1[o]; return; }
    o -= C4;
    if (o < NN * HH) {
        g_c0[0][o] = 0.f; g_c1[0][o] = 0.f;
        g_bh0[0][o] = __float2bfloat16(0.f);
        g_bh1[0][o] = __float2bfloat16(0.f);
        return;
    }
    o -= NN * HH;
    if (o < TT * NN) {
        int t = o / NN, i = o - t * NN;
        int len = g_len[i];
        const int2* cp = g_cv + (size_t)i * MAXW;
        float a0 = 0.f, a1 = 0.f;
        for (int k = 0; k < len; k++) {
            int2 cv = cp[k];
            float v = __int_as_float(cv.y);
            float2 xv = *(const float2*)&x[(size_t)t * (NN * 2) + cv.x * 2];
            a0 += v * xv.x; a1 += v * xv.y;
        }
        *(float2*)&g_AX[((size_t)t * NN + i) * 2] = make_float2(a0, a1);
    }
}
#define PREP_TOTAL (144 * C4 + 256 * C4 + 2 * C4 + NN * HH + TT * NN)

// ================= initial cell 0 (t = 0 only) =================
#define NTHR0 512
#define C0_SMEM (32 * SUP0 * 2 + 32 * CWP * 4)

__global__ __launch_bounds__(NTHR0) void k_cell0(const float* __restrict__ x, int t, int pin, int pout) {
    extern __shared__ __align__(16) char smem[];
    __nv_bfloat16* su = (__nv_bfloat16*)smem;
    float* cw = (float*)(smem + 32 * SUP0 * 2);

    const int tid  = threadIdx.x;
    const int row0 = blockIdx.x * ROWS;
    const __nv_bfloat16* __restrict__ bin = g_bh0[pin];

    {
        uint4* p = (uint4*)su;
        for (int i = tid; i < 32 * SUP0 / 8; i += NTHR0) p[i] = make_uint4(0, 0, 0, 0);
    }
    __syncthreads();

    if (tid < 448) {
        int r = tid >> 4, lane = tid & 15;
        int grow = min(row0 + r, NN - 1);
        uint2 v0 = *((const uint2*)(bin + (size_t)grow * HH) + lane);
        *(uint2*)&su[r * SUP0 + 64 + lane * 4] = v0;
    }
    if (tid < ROWS) {
        int grow = min(row0 + tid, NN - 1);
        float2 axv = *(const float2*)&g_AX[((size_t)t * NN + grow) * 2];
        float2 xv  = *(const float2*)&x[(size_t)t * (NN * 2) + grow * 2];
        *(uint2*)&su[tid * SUP0 + 128] = f4_to_b4(make_float4(axv.x, axv.y, xv.x, xv.y));
    }
    if (tid < 448) {
        int r = tid >> 4, lane = tid & 15;
        int grow = min(row0 + r, NN - 1);
        int len = g_len[grow];
        const int2* cb = g_cv + (size_t)grow * MAXW;
        float4 a4 = make_float4(0.f, 0.f, 0.f, 0.f);
        #pragma unroll 4
        for (int k = 0; k < len; k++) {
            int2 cv = __ldg(&cb[k]);
            gacc(a4, __int_as_float(cv.y), bin, cv.x, lane);
        }
        *(uint2*)&su[r * SUP0 + lane * 4] = f4_to_b4(a4);
    }
    __syncthreads();

    {
        const int w = tid >> 5, tl = tid & 31;
        const int mt = w & 1, nc = w >> 1;
        const int rA = mt * 16 + (tl >> 2);
        const int cA = 2 * (tl & 3);
        float c[4][4];
        #pragma unroll
        for (int j = 0; j < 4; j++) { c[j][0] = c[j][1] = c[j][2] = c[j][3] = 0.f; }
        #pragma unroll 1
        for (int kt = 0; kt < NKT0; kt++) {
            unsigned a0 = *(const unsigned*)&su[rA * SUP0 + kt * 16 + cA];
            unsigned a1 = *(const unsigned*)&su[(rA + 8) * SUP0 + kt * 16 + cA];
            unsigned a2 = *(const unsigned*)&su[rA * SUP0 + kt * 16 + cA + 8];
            unsigned a3 = *(const unsigned*)&su[(rA + 8) * SUP0 + kt * 16 + cA + 8];
            #pragma unroll
            for (int j = 0; j < 4; j++) {
                int nt = nc * 4 + j;
                uint2 b = __ldg((const uint2*)g_Wp0 + (nt * NKT0 + kt) * 32 + tl);
                mma_bf16(c[j], a0, a1, a2, a3, b.x, b.y);
            }
        }
        int r = mt * 16 + (tl >> 2);
        #pragma unroll
        for (int j = 0; j < 4; j++) {
            int n = nc * 32 + j * 8 + 2 * (tl & 3);
            float2 bb = *(const float2*)&g_b0[n];
            cw[r * CWP + n]           = c[j][0] + bb.x;
            cw[r * CWP + n + 1]       = c[j][1] + bb.y;
            cw[(r + 8) * CWP + n]     = c[j][2] + bb.x;
            cw[(r + 8) * CWP + n + 1] = c[j][3] + bb.y;
        }
    }
    __syncthreads();

    const float* __restrict__ cold = g_c0[pin];
    float* __restrict__ cn = g_c0[pout];
    __nv_bfloat16* __restrict__ bo = g_bh0[pout];
    for (int i = tid; i < ROWS * HH; i += NTHR0) {
        int r = i >> 6, h = i & 63;
        int grow = row0 + r;
        if (grow < NN) {
            float ig = cw[r * CWP + h],       fg = cw[r * CWP + 64 + h];
            float og = cw[r * CWP + 128 + h], gg = cw[r * CWP + 192 + h];
            size_t gi = (size_t)grow * HH + h;
            float cvv = sigf(fg) * cold[gi] + sigf(ig) * tanhf2(gg);
            cn[gi] = cvv;
            bo[gi] = __float2bfloat16(sigf(og) * tanhf2(cvv));
        }
    }
}

// ================= fused step: cell1(t) + cell0(t+1), PDL-overlapped =================
// smem: su1 bf16[32][SUP1] | su0 bf16[32][SUP0] | cw1 f32[32][CWP] | cw0 f32[32][CWP]
#define O_SU0 (32 * SUP1 * 2)
#define O_CW1 (O_SU0 + 32 * SUP0 * 2)
#define O_CW0 (O_CW1 + 32 * CWP * 4)
#define STEP_SMEM (O_CW0 + 32 * CWP * 4)

__global__ __launch_bounds__(1024) void k_step(const float* __restrict__ x,
                                               const float* __restrict__ outW,
                                               const float* __restrict__ outb,
                                               float* __restrict__ out, int t) {
    extern __shared__ __align__(16) char smem[];
    __nv_bfloat16* su1 = (__nv_bfloat16*)smem;
    __nv_bfloat16* su0 = (__nv_bfloat16*)(smem + O_SU0);
    float* cw1 = (float*)(smem + O_CW1);
    float* cw0 = (float*)(smem + O_CW0);
    float* hl  = (float*)(smem + O_SU0);      // aliases su0 (last step only)

    const int tid  = threadIdx.x;
    const int row0 = blockIdx.x * ROWS;
    const int pin = t & 1, pout = pin ^ 1;
    const bool last = (t == TT - 1);
    const __nv_bfloat16* __restrict__ bh0n = g_bh0[pout];   // new h0 (from prev launch)
    const __nv_bfloat16* __restrict__ bh1o = g_bh1[pin];    // old h1

    // ---------- PRE-SYNC PROLOGUE: depends only on static data ----------
    // zero su1 + su0
    {
        uint4* p = (uint4*)smem;
        for (int i = tid; i < (32 * SUP1 + 32 * SUP0) / 8; i += 1024) p[i] = make_uint4(0, 0, 0, 0);
    }
    // early B-fragment prefetch (static weights)
    const int w = tid >> 5, tl = tid & 31;
    const int mt = w & 1, nq = w >> 1;
    const uint2* p1 = (const uint2*)g_Wp1 + (nq * 2 * NKT1) * 32 + tl;   // n-tiles 2nq, 2nq+1
    const uint2* p0 = (const uint2*)g_Wp0 + (nq * 2 * NKT0) * 32 + tl;
    uint2 b1a = __ldg(p1), b1b = __ldg(p1 + NKT1 * 32);
    uint2 b0a = make_uint2(0, 0), b0b = make_uint2(0, 0);
    if (!last) { b0a = __ldg(p0); b0b = __ldg(p0 + NKT0 * 32); }
    __syncthreads();
    // x-term staging (static g_AX / x)
    if (tid < ROWS && !last) {
        int grow = min(row0 + tid, NN - 1);
        float2 axv = *(const float2*)&g_AX[((size_t)(t + 1) * NN + grow) * 2];
        float2 xv  = *(const float2*)&x[(size_t)(t + 1) * (NN * 2) + grow * 2];
        *(uint2*)&su0[tid * SUP0 + 128] = f4_to_b4(make_float4(axv.x, axv.y, xv.x, xv.y));
    }

    // ---------- wait for previous step's global writes ----------
    cudaGridDependencySynchronize();

    // direct operands (previous step's h outputs)
    if (tid < 448) {
        int r = tid >> 4, lane = tid & 15;
        int grow = min(row0 + r, NN - 1);
        uint2 v0 = *((const uint2*)(bh0n + (size_t)grow * HH) + lane);
        uint2 v1 = *((const uint2*)(bh1o + (size_t)grow * HH) + lane);
        *(uint2*)&su1[r * SUP1 + 64 + lane * 4]  = v0;
        *(uint2*)&su1[r * SUP1 + 192 + lane * 4] = v1;
        *(uint2*)&su0[r * SUP0 + 64 + lane * 4]  = v0;
    }
    // shared gather, batch-of-4 index prefetch
    if (tid < 896) {
        int r = tid >> 5, half = (tid >> 4) & 1, lane = tid & 15;
        int grow = min(row0 + r, NN - 1);
        int len = g_len[grow];
        const int2* cb = g_cv + (size_t)grow * MAXW;
        float4 a0 = make_float4(0.f, 0.f, 0.f, 0.f);
        float4 a1 = make_float4(0.f, 0.f, 0.f, 0.f);
        int k = half;
        for (; k + 6 < len; k += 8) {
            int2 v0 = __ldg(&cb[k]);
            int2 v1 = __ldg(&cb[k + 2]);
            int2 v2 = __ldg(&cb[k + 4]);
            int2 v3 = __ldg(&cb[k + 6]);
            float f0 = __int_as_float(v0.y), f1 = __int_as_float(v1.y);
            float f2 = __int_as_float(v2.y), f3 = __int_as_float(v3.y);
            gacc(a0, f0, bh0n, v0.x, lane); gacc(a1, f0, bh1o, v0.x, lane);
            gacc(a0, f1, bh0n, v1.x, lane); gacc(a1, f1, bh1o, v1.x, lane);
            gacc(a0, f2, bh0n, v2.x, lane); gacc(a1, f2, bh1o, v2.x, lane);
            gacc(a0, f3, bh0n, v3.x, lane); gacc(a1, f3, bh1o, v3.x, lane);
        }
        for (; k < len; k += 2) {
            int2 v = __ldg(&cb[k]);
            float f = __int_as_float(v.y);
            gacc(a0, f, bh0n, v.x, lane); gacc(a1, f, bh1o, v.x, lane);
        }
        a0.x += __shfl_xor_sync(0xffffffffu, a0.x, 16);
        a0.y += __shfl_xor_sync(0xffffffffu, a0.y, 16);
        a0.z += __shfl_xor_sync(0xffffffffu, a0.z, 16);
        a0.w += __shfl_xor_sync(0xffffffffu, a0.w, 16);
        a1.x += __shfl_xor_sync(0xffffffffu, a1.x, 16);
        a1.y += __shfl_xor_sync(0xffffffffu, a1.y, 16);
        a1.z += __shfl_xor_sync(0xffffffffu, a1.z, 16);
        a1.w += __shfl_xor_sync(0xffffffffu, a1.w, 16);
        if (half == 0) {
            uint2 q0 = f4_to_b4(a0), q1 = f4_to_b4(a1);
            *(uint2*)&su1[r * SUP1 + lane * 4]       = q0;
            *(uint2*)&su0[r * SUP0 + lane * 4]       = q0;
            *(uint2*)&su1[r * SUP1 + 128 + lane * 4] = q1;
        }
    }
    __syncthreads();

    // merged MMA: cell1 (16 kt) with cell0 (9 kt) interleaved, both streams prefetched
    const int rA = mt * 16 + (tl >> 2), cA = 2 * (tl & 3);
    float c1r[2][4], c0r[2][4];
    #pragma unroll
    for (int j = 0; j < 2; j++)
        #pragma unroll
        for (int q = 0; q < 4; q++) { c1r[j][q] = 0.f; c0r[j][q] = 0.f; }
    #pragma unroll 1
    for (int kt = 0; kt < NKT1; kt++) {
        uint2 n1a = make_uint2(0, 0), n1b = n1a, n0a = n1a, n0b = n1a;
        if (kt + 1 < NKT1) {
            n1a = __ldg(p1 + (kt + 1) * 32);
            n1b = __ldg(p1 + (NKT1 + kt + 1) * 32);
        }
        if (!last && kt + 1 < NKT0) {
            n0a = __ldg(p0 + (kt + 1) * 32);
            n0b = __ldg(p0 + (NKT0 + kt + 1) * 32);
        }
        unsigned a0 = *(const unsigned*)&su1[rA * SUP1 + kt * 16 + cA];
        unsigned a1 = *(const unsigned*)&su1[(rA + 8) * SUP1 + kt * 16 + cA];
        unsigned a2 = *(const unsigned*)&su1[rA * SUP1 + kt * 16 + cA + 8];
        unsigned a3 = *(const unsigned*)&su1[(rA + 8) * SUP1 + kt * 16 + cA + 8];
        mma_bf16(c1r[0], a0, a1, a2, a3, b1a.x, b1a.y);
        mma_bf16(c1r[1], a0, a1, a2, a3, b1b.x, b1b.y);
        if (!last && kt < NKT0) {
            unsigned d0 = *(const unsigned*)&su0[rA * SUP0 + kt * 16 + cA];
            unsigned d1 = *(const unsigned*)&su0[(rA + 8) * SUP0 + kt * 16 + cA];
            unsigned d2 = *(const unsigned*)&su0[rA * SUP0 + kt * 16 + cA + 8];
            unsigned d3 = *(const unsigned*)&su0[(rA + 8) * SUP0 + kt * 16 + cA + 8];
            mma_bf16(c0r[0], d0, d1, d2, d3, b0a.x, b0a.y);
            mma_bf16(c0r[1], d0, d1, d2, d3, b0b.x, b0b.y);
        }
        b1a = n1a; b1b = n1b; b0a = n0a; b0b = n0b;
    }
    {   // write combs (+bias)
        int r = mt * 16 + (tl >> 2);
        #pragma unroll
        for (int j = 0; j < 2; j++) {
            int n = nq * 16 + j * 8 + 2 * (tl & 3);
            float2 bb1 = *(const float2*)&g_b1[n];
            cw1[r * CWP + n]           = c1r[j][0] + bb1.x;
            cw1[r * CWP + n + 1]       = c1r[j][1] + bb1.y;
            cw1[(r + 8) * CWP + n]     = c1r[j][2] + bb1.x;
            cw1[(r + 8) * CWP + n + 1] = c1r[j][3] + bb1.y;
            if (!last) {
                float2 bb0 = *(const float2*)&g_b0[n];
                cw0[r * CWP + n]           = c0r[j][0] + bb0.x;
                cw0[r * CWP + n + 1]       = c0r[j][1] + bb0.y;
                cw0[(r + 8) * CWP + n]     = c0r[j][2] + bb0.x;
                cw0[(r + 8) * CWP + n + 1] = c0r[j][3] + bb0.y;
            }
        }
    }
    __syncthreads();

    // only the epilogue remains -> let the next step begin its prologue
    cudaTriggerProgrammaticLaunchCompletion();

    // epilogue cell1(t)
    {
        const float* __restrict__ cold = g_c1[pin];
        float* __restrict__ cn = g_c1[pout];
        __nv_bfloat16* __restrict__ bo = g_bh1[pout];
        #pragma unroll
        for (int it = 0; it < 2; it++) {
            int i = tid + it * 1024;
            if (i < ROWS * HH) {
                int r = i >> 6, h = i & 63;
                int grow = row0 + r;
                if (grow < NN) {
                    float ig = cw1[r * CWP + h],       fg = cw1[r * CWP + 64 + h];
                    float og = cw1[r * CWP + 128 + h], gg = cw1[r * CWP + 192 + h];
                    size_t gi = (size_t)grow * HH + h;
                    float cvv = sigf(fg) * cold[gi] + sigf(ig) * tanhf2(gg);
                    cn[gi] = cvv;
                    float hv = sigf(og) * tanhf2(cvv);
                    bo[gi] = __float2bfloat16(hv);
                    if (last) hl[r * 64 + h] = hv;
                }
            }
        }
    }
    if (!last) {
        // epilogue cell0(t+1): pin' = pout, pout' = pin
        const float* __restrict__ cold = g_c0[pout];
        float* __restrict__ cn = g_c0[pin];
        __nv_bfloat16* __restrict__ bo = g_bh0[pin];
        #pragma unroll
        for (int it = 0; it < 2; it++) {
            int i = tid + it * 1024;
            if (i < ROWS * HH) {
                int r = i >> 6, h = i & 63;
                int grow = row0 + r;
                if (grow < NN) {
                    float ig = cw0[r * CWP + h],       fg = cw0[r * CWP + 64 + h];
                    float og = cw0[r * CWP + 128 + h], gg = cw0[r * CWP + 192 + h];
                    size_t gi = (size_t)grow * HH + h;
                    float cvv = sigf(fg) * cold[gi] + sigf(ig) * tanhf2(gg);
                    cn[gi] = cvv;
                    bo[gi] = __float2bfloat16(sigf(og) * tanhf2(cvv));
                }
            }
        }
    } else {
        // output projection from fp32 h1 in smem
        __syncthreads();
        if (tid < ROWS * 12) {
            int r = tid / 12, p = tid - r * 12;
            int grow = row0 + r;
            if (grow < NN) {
                float s = outb[p];
                #pragma unroll
                for (int k = 0; k < HH; k++) s += hl[r * 64 + k] * outW[k * 12 + p];
                out[grow * 12 + p] = s;
            }
        }
    }
}

extern "C" void kernel_launch(void* const* d_in, const int* in_sizes, int n_in,
                              void* d_out, int out_size) {
    const float* x     = (const float*)d_in[0];
    const float* adj   = (const float*)d_in[1];
    const float* gcWi0 = (const float*)d_in[2];
    const float* gcbi0 = (const float*)d_in[3];
    const float* gcWh0 = (const float*)d_in[4];
    const float* gcbh0 = (const float*)d_in[5];
    const float* liWi0 = (const float*)d_in[6];
    const float* libi0 = (const float*)d_in[7];
    const float* liWh0 = (const float*)d_in[8];
    const float* libh0 = (const float*)d_in[9];
    const float* gcWi1 = (const float*)d_in[10];
    const float* gcbi1 = (const float*)d_in[11];
    const float* gcWh1 = (const float*)d_in[12];
    const float* gcbh1 = (const float*)d_in[13];
    const float* liWi1 = (const float*)d_in[14];
    const float* libi1 = (const float*)d_in[15];
    const float* liWh1 = (const float*)d_in[16];
    const float* libh1 = (const float*)d_in[17];
    const float* outW  = (const float*)d_in[18];
    const float* outb  = (const float*)d_in[19];
    float* out = (float*)d_out;

    cudaFuncSetAttribute(k_cell0, cudaFuncAttributeMaxDynamicSharedMemorySize, C0_SMEM);
    cudaFuncSetAttribute(k_step, cudaFuncAttributeMaxDynamicSharedMemorySize, STEP_SMEM);

    k_dinv<<<NN / 8, 256>>>(adj);
    k_build<<<NN / 8, 256>>>(adj);
    k_prep<<<(PREP_TOTAL + 255) / 256, 256>>>(x,
        gcWi0, gcWh0, liWi0, liWh0, gcWi1, liWi1, gcWh1, liWh1,
        gcbi0, gcbh0, libi0, libh0, gcbi1, gcbh1, libi1, libh1);

    k_cell0<<<GRID, NTHR0, C0_SMEM>>>(x, 0, 0, 1);           // cell0 of step 0

    cudaLaunchConfig_t cfg = {};
    cfg.gridDim = dim3(GRID, 1, 1);
    cfg.blockDim = dim3(1024, 1, 1);
    cfg.dynamicSmemBytes = STEP_SMEM;
    cfg.stream = 0;
    cudaLaunchAttribute attrs[1];
    attrs[0].id = cudaLaunchAttributeProgrammaticStreamSerialization;
    attrs[0].val.programmaticStreamSerializationAllowed = 1;
    cfg.attrs = attrs;
    cfg.numAttrs = 1;
    for (int t = 0; t < TT; t++)
        cudaLaunchKernelEx(&cfg, k_step, x, outW, outb, out, t);  // cell1(t) + cell0(t+1)
}

// round 16
// speedup vs baseline: 1.1622x; 1.1325x over previous
#include <cuda_runtime.h>
#include <cuda_bf16.h>

#define NN   4096
#define TT   48
#define HH   64
#define C4   256
#define MAXW 128
#define ROWS 28
#define GRID 147

#define RPB   14                      // rows per k_step block
#define GRID2 ((NN + RPB - 1) / RPB)  // 293

#define SUP0 152      // su pitch (bf16) cell0: K=144 + 8 pad
#define NKT0 9        // 144/16
#define SUP1 264      // su pitch (bf16) cell1: K=256 + 8 pad
#define NKT1 16
#define CWP  260      // comb pitch (fp32) — initial cell0 only

// ---------------- device scratch (no allocations allowed) ----------------
__device__ __align__(16) float g_dinv[NN];
__device__ __align__(16) int2  g_cv[NN * MAXW];    // (col, __float_as_int(val))
__device__ __align__(16) int   g_len[NN];
__device__ __align__(16) float g_AX[TT * NN * 2];
__device__ __align__(16) __nv_bfloat16 g_Wp0[144 * C4];  // fragment-packed [gcWh0;liWh0;Wx;0]
__device__ __align__(16) __nv_bfloat16 g_Wp1[256 * C4];  // fragment-packed [gcWi1;liWi1;gcWh1;liWh1]
__device__ __align__(16) float g_b0[C4];
__device__ __align__(16) float g_b1[C4];
__device__ __align__(16) float g_c0[2][NN * HH];
__device__ __align__(16) float g_c1[2][NN * HH];
__device__ __align__(16) __nv_bfloat16 g_bh0[2][NN * HH];  // bf16 h mirrors
__device__ __align__(16) __nv_bfloat16 g_bh1[2][NN * HH];

// ---------------- helpers ----------------
__device__ __forceinline__ float sigf(float v)  { return 1.f / (1.f + __expf(-v)); }
__device__ __forceinline__ float tanhf2(float v){ return 2.f / (1.f + __expf(-2.f * v)) - 1.f; }

__device__ __forceinline__ void gacc(float4& a, float v, const __nv_bfloat16* bh, int c, int lane) {
    uint2 raw = *((const uint2*)(bh + (size_t)c * HH) + lane);
    __nv_bfloat162 b01 = *(__nv_bfloat162*)&raw.x;
    __nv_bfloat162 b23 = *(__nv_bfloat162*)&raw.y;
    float2 f01 = __bfloat1622float2(b01), f23 = __bfloat1622float2(b23);
    a.x += v * f01.x; a.y += v * f01.y; a.z += v * f23.x; a.w += v * f23.y;
}

__device__ __forceinline__ uint2 f4_to_b4(float4 a) {
    __nv_bfloat162 lo = __floats2bfloat162_rn(a.x, a.y);
    __nv_bfloat162 hi = __floats2bfloat162_rn(a.z, a.w);
    uint2 r; r.x = *(unsigned*)&lo; r.y = *(unsigned*)&hi; return r;
}

__device__ __forceinline__ void mma_bf16(float* c, unsigned a0, unsigned a1, unsigned a2, unsigned a3,
                                         unsigned b0, unsigned b1) {
    asm volatile("mma.sync.aligned.m16n8k16.row.col.f32.bf16.bf16.f32 "
                 "{%0,%1,%2,%3},{%4,%5,%6,%7},{%8,%9},{%0,%1,%2,%3};"
                 : "+f"(c[0]), "+f"(c[1]), "+f"(c[2]), "+f"(c[3])
                 : "r"(a0), "r"(a1), "r"(a2), "r"(a3), "r"(b0), "r"(b1));
}

__host__ __device__ __forceinline__ int fragoff(int k, int n, int nkt) {
    int kt = k >> 4, kr = k & 15, nt = n >> 3, nr = n & 7;
    int t = nr * 4 + ((kr & 7) >> 1);
    int pos = t * 4 + ((kr >> 3) << 1) + (kr & 1);
    return ((nt * nkt + kt) << 7) + pos;
}

// ---------------- setup kernels ----------------
__global__ void k_dinv(const float* __restrict__ adj) {
    int row  = blockIdx.x * 8 + (threadIdx.x >> 5);
    int lane = threadIdx.x & 31;
    if (row >= NN) return;
    float s = 0.f;
    for (int j = lane; j < NN; j += 32) s += adj[(size_t)row * NN + j];
    #pragma unroll
    for (int o = 16; o; o >>= 1) s += __shfl_xor_sync(0xffffffffu, s, o);
    if (lane == 0) g_dinv[row] = rsqrtf(s + 1.f);   // A = adj + I
}

__global__ void k_build(const float* __restrict__ adj) {
    int row  = blockIdx.x * 8 + (threadIdx.x >> 5);
    int lane = threadIdx.x & 31;
    if (row >= NN) return;
    float dr = g_dinv[row];
    int base = 0;
    for (int j0 = 0; j0 < NN; j0 += 32) {
        int   j    = j0 + lane;
        float v    = adj[(size_t)row * NN + j];
        bool  pres = (v != 0.f) || (j == row);
        float aval = v + ((j == row) ? 1.f : 0.f);
        unsigned m = __ballot_sync(0xffffffffu, pres);
        if (pres) {
            int pos = base + __popc(m & ((1u << lane) - 1u));
            if (pos < MAXW)
                g_cv[row * MAXW + pos] = make_int2(j, __float_as_int(aval * dr * g_dinv[j]));
        }
        base += __popc(m);
    }
    if (base > MAXW) base = MAXW;
    if (lane == 0) g_len[row] = base;
}

__global__ void k_prep(const float* __restrict__ x,
                       const float* gcWi0, const float* gcWh0, const float* liWi0, const float* liWh0,
                       const float* gcWi1, const float* liWi1, const float* gcWh1, const float* liWh1,
                       const float* bi0, const float* bh0, const float* lbi0, const float* lbh0,
                       const float* bi1, const float* bh1, const float* lbi1, const float* lbh1) {
    int idx = blockIdx.x * blockDim.x + threadIdx.x;
    const int W0E = 144 * C4, W1E = 256 * C4;
    int o = idx;
    if (o < W0E) {
        int k = o >> 8, n = o & 255;
        float v;
        if (k < 64)       v = gcWh0[k * C4 + n];
        else if (k < 128) v = liWh0[(k - 64) * C4 + n];
        else {
            int q = k - 128;
            v = (q < 2) ? gcWi0[q * C4 + n] : (q < 4) ? liWi0[(q - 2) * C4 + n] : 0.f;
        }
        g_Wp0[fragoff(k, n, NKT0)] = __float2bfloat16(v);
        return;
    }
    o -= W0E;
    if (o < W1E) {
        int k = o >> 8, n = o & 255;
        int seg = k >> 6, rr = k & 63;
        const float* s = (seg == 0) ? gcWi1 : (seg == 1) ? liWi1 : (seg == 2) ? gcWh1 : liWh1;
        g_Wp1[fragoff(k, n, NKT1)] = __float2bfloat16(s[rr * C4 + n]);
        return;
    }
    o -= W1E;
    if (o < C4) { g_b0[o] = bi0[o] + bh0[o] + lbi0[o] + lbh0[o]; return; }
    o -= C4;
    if (o < C4) { g_b1[o] = bi1[o] + bh1[o] + lbi1[o] + lbh1[o]; return; }
    o -= C4;
    if (o < NN * HH) {
        g_c0[0][o] = 0.f; g_c1[0][o] = 0.f;
        g_bh0[0][o] = __float2bfloat16(0.f);
        g_bh1[0][o] = __float2bfloat16(0.f);
        return;
    }
    o -= NN * HH;
    if (o < TT * NN) {
        int t = o / NN, i = o - t * NN;
        int len = g_len[i];
        const int2* cp = g_cv + (size_t)i * MAXW;
        float a0 = 0.f, a1 = 0.f;
        for (int k = 0; k < len; k++) {
            int2 cv = cp[k];
            float v = __int_as_float(cv.y);
            float2 xv = *(const float2*)&x[(size_t)t * (NN * 2) + cv.x * 2];
            a0 += v * xv.x; a1 += v * xv.y;
        }
        *(float2*)&g_AX[((size_t)t * NN + i) * 2] = make_float2(a0, a1);
    }
}
#define PREP_TOTAL (144 * C4 + 256 * C4 + 2 * C4 + NN * HH + TT * NN)

// ================= initial cell 0 (t = 0 only; unchanged proven path) =================
#define NTHR0 512
#define C0_SMEM (32 * SUP0 * 2 + 32 * CWP * 4)

__global__ __launch_bounds__(NTHR0) void k_cell0(const float* __restrict__ x, int t, int pin, int pout) {
    extern __shared__ __align__(16) char smem[];
    __nv_bfloat16* su = (__nv_bfloat16*)smem;
    float* cw = (float*)(smem + 32 * SUP0 * 2);

    const int tid  = threadIdx.x;
    const int row0 = blockIdx.x * ROWS;
    const __nv_bfloat16* __restrict__ bin = g_bh0[pin];

    {
        uint4* p = (uint4*)su;
        for (int i = tid; i < 32 * SUP0 / 8; i += NTHR0) p[i] = make_uint4(0, 0, 0, 0);
    }
    __syncthreads();

    if (tid < 448) {
        int r = tid >> 4, lane = tid & 15;
        int grow = min(row0 + r, NN - 1);
        uint2 v0 = *((const uint2*)(bin + (size_t)grow * HH) + lane);
        *(uint2*)&su[r * SUP0 + 64 + lane * 4] = v0;
    }
    if (tid < ROWS) {
        int grow = min(row0 + tid, NN - 1);
        float2 axv = *(const float2*)&g_AX[((size_t)t * NN + grow) * 2];
        float2 xv  = *(const float2*)&x[(size_t)t * (NN * 2) + grow * 2];
        *(uint2*)&su[tid * SUP0 + 128] = f4_to_b4(make_float4(axv.x, axv.y, xv.x, xv.y));
    }
    if (tid < 448) {
        int r = tid >> 4, lane = tid & 15;
        int grow = min(row0 + r, NN - 1);
        int len = g_len[grow];
        const int2* cb = g_cv + (size_t)grow * MAXW;
        float4 a4 = make_float4(0.f, 0.f, 0.f, 0.f);
        #pragma unroll 4
        for (int k = 0; k < len; k++) {
            int2 cv = __ldg(&cb[k]);
            gacc(a4, __int_as_float(cv.y), bin, cv.x, lane);
        }
        *(uint2*)&su[r * SUP0 + lane * 4] = f4_to_b4(a4);
    }
    __syncthreads();

    {
        const int w = tid >> 5, tl = tid & 31;
        const int mt = w & 1, nc = w >> 1;
        const int rA = mt * 16 + (tl >> 2);
        const int cA = 2 * (tl & 3);
        float c[4][4];
        #pragma unroll
        for (int j = 0; j < 4; j++) { c[j][0] = c[j][1] = c[j][2] = c[j][3] = 0.f; }
        #pragma unroll 1
        for (int kt = 0; kt < NKT0; kt++) {
            unsigned a0 = *(const unsigned*)&su[rA * SUP0 + kt * 16 + cA];
            unsigned a1 = *(const unsigned*)&su[(rA + 8) * SUP0 + kt * 16 + cA];
            unsigned a2 = *(const unsigned*)&su[rA * SUP0 + kt * 16 + cA + 8];
            unsigned a3 = *(const unsigned*)&su[(rA + 8) * SUP0 + kt * 16 + cA + 8];
            #pragma unroll
            for (int j = 0; j < 4; j++) {
                int nt = nc * 4 + j;
                uint2 b = __ldg((const uint2*)g_Wp0 + (nt * NKT0 + kt) * 32 + tl);
                mma_bf16(c[j], a0, a1, a2, a3, b.x, b.y);
            }
        }
        int r = mt * 16 + (tl >> 2);
        #pragma unroll
        for (int j = 0; j < 4; j++) {
            int n = nc * 32 + j * 8 + 2 * (tl & 3);
            float2 bb = *(const float2*)&g_b0[n];
            cw[r * CWP + n]           = c[j][0] + bb.x;
            cw[r * CWP + n + 1]       = c[j][1] + bb.y;
            cw[(r + 8) * CWP + n]     = c[j][2] + bb.x;
            cw[(r + 8) * CWP + n + 1] = c[j][3] + bb.y;
        }
    }
    __syncthreads();

    const float* __restrict__ cold = g_c0[pin];
    float* __restrict__ cn = g_c0[pout];
    __nv_bfloat16* __restrict__ bo = g_bh0[pout];
    for (int i = tid; i < ROWS * HH; i += NTHR0) {
        int r = i >> 6, h = i & 63;
        int grow = row0 + r;
        if (grow < NN) {
            float ig = cw[r * CWP + h],       fg = cw[r * CWP + 64 + h];
            float og = cw[r * CWP + 128 + h], gg = cw[r * CWP + 192 + h];
            size_t gi = (size_t)grow * HH + h;
            float cvv = sigf(fg) * cold[gi] + sigf(ig) * tanhf2(gg);
            cn[gi] = cvv;
            bo[gi] = __float2bfloat16(sigf(og) * tanhf2(cvv));
        }
    }
}

// ================= fused step: cell1(t) + cell0(t+1) =================
// 512 threads, 14 rows, 2 blocks/SM; register epilogue (gate-aligned warps)
// smem: su1 bf16[16][SUP1] | su0 bf16[16][SUP0]  (su0 aliased by hl f32[16][64] on last step)
#define S2_SU0  (16 * SUP1 * 2)
#define STEP_SMEM (S2_SU0 + 16 * SUP0 * 2)

__global__ void __launch_bounds__(512, 2) k_step(const float* __restrict__ x,
                                                 const float* __restrict__ outW,
                                                 const float* __restrict__ outb,
                                                 float* __restrict__ out, int t) {
    extern __shared__ __align__(16) char smem[];
    __nv_bfloat16* su1 = (__nv_bfloat16*)smem;
    __nv_bfloat16* su0 = (__nv_bfloat16*)(smem + S2_SU0);
    float* hl = (float*)(smem + S2_SU0);      // last step only

    const int tid  = threadIdx.x;
    const int row0 = blockIdx.x * RPB;
    const int pin = t & 1, pout = pin ^ 1;
    const bool last = (t == TT - 1);
    const __nv_bfloat16* __restrict__ bh0n = g_bh0[pout];   // new h0 (prev launch)
    const __nv_bfloat16* __restrict__ bh1o = g_bh1[pin];    // old h1

    const int wid = tid >> 5, tl = tid & 31;
    const bool is1 = (wid < 8);                // warps 0-7: cell1; 8-15: cell0
    const int jg = is1 ? wid : (wid - 8);      // gate column group 0..7
    const int rA = tl >> 2, cA = 2 * (tl & 3);
    const int hb = jg * 8 + cA;                // h columns hb, hb+1

    // ---------- PRE-SYNC: static-only work ----------
    {   // zero su (pads + gather targets)
        uint4* p = (uint4*)smem;
        for (int i = tid; i < STEP_SMEM / 16; i += 512) p[i] = make_uint4(0, 0, 0, 0);
    }
    // B-fragment pointers + first prefetch (static weights)
    const __nv_bfloat16* Wme = is1 ? g_Wp1 : g_Wp0;
    const int nktme = is1 ? NKT1 : NKT0;
    const uint2* pB[4];
    uint2 bcur[4];
    #pragma unroll
    for (int g = 0; g < 4; g++) {
        pB[g] = (const uint2*)Wme + ((g * 8 + jg) * nktme) * 32 + tl;
        bcur[g] = __ldg(pB[g]);
    }
    // bias-initialized accumulators
    float c[4][4];
    {
        const float* bme = is1 ? g_b1 : g_b0;
        #pragma unroll
        for (int g = 0; g < 4; g++) {
            float2 bb = *(const float2*)&bme[g * 64 + hb];
            c[g][0] = bb.x; c[g][1] = bb.y; c[g][2] = bb.x; c[g][3] = bb.y;
        }
    }
    __syncthreads();          // zero-fill visible before staging/gather writes

    // ---------- wait for previous step ----------
    cudaGridDependencySynchronize();

    // stage direct h operands (rows 0..13)
    if (tid < 224) {
        int r = tid >> 4, lane = tid & 15;
        int grow = min(row0 + r, NN - 1);
        uint2 v0 = *((const uint2*)(bh0n + (size_t)grow * HH) + lane);
        uint2 v1 = *((const uint2*)(bh1o + (size_t)grow * HH) + lane);
        *(uint2*)&su1[r * SUP1 + 64 + lane * 4]  = v0;
        *(uint2*)&su1[r * SUP1 + 192 + lane * 4] = v1;
        *(uint2*)&su0[r * SUP0 + 64 + lane * 4]  = v0;
    }
    // x-term for cell0(t+1) (idle threads; static reads)
    if (tid >= 448 && tid < 448 + RPB && !last) {
        int r = tid - 448;
        int grow = row0 + r;
        if (grow < NN) {
            float2 axv = *(const float2*)&g_AX[((size_t)(t + 1) * NN + grow) * 2];
            float2 xv  = *(const float2*)&x[(size_t)(t + 1) * (NN * 2) + grow * 2];
            *(uint2*)&su0[r * SUP0 + 128] = f4_to_b4(make_float4(axv.x, axv.y, xv.x, xv.y));
        }
    }
    // shared gather: a0 = A@h0n (both cells), a1 = A@h1o; split-k over 2 halves
    if (tid < 448) {
        int r = tid >> 5, half = (tid >> 4) & 1, lane = tid & 15;
        int grow = min(row0 + r, NN - 1);
        int len = g_len[grow];
        const int2* cb = g_cv + (size_t)grow * MAXW;
        float4 a0 = make_float4(0.f, 0.f, 0.f, 0.f);
        float4 a1 = make_float4(0.f, 0.f, 0.f, 0.f);
        int k = half;
        for (; k + 6 < len; k += 8) {
            int2 v0 = __ldg(&cb[k]);
            int2 v1 = __ldg(&cb[k + 2]);
            int2 v2 = __ldg(&cb[k + 4]);
            int2 v3 = __ldg(&cb[k + 6]);
            float f0 = __int_as_float(v0.y), f1 = __int_as_float(v1.y);
            float f2 = __int_as_float(v2.y), f3 = __int_as_float(v3.y);
            gacc(a0, f0, bh0n, v0.x, lane); gacc(a1, f0, bh1o, v0.x, lane);
            gacc(a0, f1, bh0n, v1.x, lane); gacc(a1, f1, bh1o, v1.x, lane);
            gacc(a0, f2, bh0n, v2.x, lane); gacc(a1, f2, bh1o, v2.x, lane);
            gacc(a0, f3, bh0n, v3.x, lane); gacc(a1, f3, bh1o, v3.x, lane);
        }
        for (; k < len; k += 2) {
            int2 v = __ldg(&cb[k]);
            float f = __int_as_float(v.y);
            gacc(a0, f, bh0n, v.x, lane); gacc(a1, f, bh1o, v.x, lane);
        }
        a0.x += __shfl_xor_sync(0xffffffffu, a0.x, 16);
        a0.y += __shfl_xor_sync(0xffffffffu, a0.y, 16);
        a0.z += __shfl_xor_sync(0xffffffffu, a0.z, 16);
        a0.w += __shfl_xor_sync(0xffffffffu, a0.w, 16);
        a1.x += __shfl_xor_sync(0xffffffffu, a1.x, 16);
        a1.y += __shfl_xor_sync(0xffffffffu, a1.y, 16);
        a1.z += __shfl_xor_sync(0xffffffffu, a1.z, 16);
        a1.w += __shfl_xor_sync(0xffffffffu, a1.w, 16);
        if (half == 0) {
            uint2 q0 = f4_to_b4(a0), q1 = f4_to_b4(a1);
            *(uint2*)&su1[r * SUP1 + lane * 4]       = q0;
            *(uint2*)&su0[r * SUP0 + lane * 4]       = q0;
            *(uint2*)&su1[r * SUP1 + 128 + lane * 4] = q1;
        }
    }
    // prefetch c-state for this thread's epilogue slots
    float2 cold0 = make_float2(0.f, 0.f), cold1 = cold0;
    {
        const float* cme = is1 ? g_c1[pin] : g_c0[pout];
        int g0 = row0 + rA, g1 = row0 + rA + 8;
        if ((is1 || !last) && rA < RPB && g0 < NN) cold0 = *(const float2*)&cme[(size_t)g0 * HH + hb];
        if ((is1 || !last) && rA + 8 < RPB && g1 < NN) cold1 = *(const float2*)&cme[(size_t)g1 * HH + hb];
    }
    __syncthreads();

    // ---------- MMA (cell1 in warps 0-7, cell0 in warps 8-15, concurrent) ----------
    const __nv_bfloat16* sume = is1 ? su1 : su0;
    const int pit = is1 ? SUP1 : SUP0;
    if (is1 || !last) {
        #pragma unroll 1
        for (int kt = 0; kt < nktme; kt++) {
            uint2 bn[4];
            if (kt + 1 < nktme) {
                #pragma unroll
                for (int g = 0; g < 4; g++) bn[g] = __ldg(pB[g] + (kt + 1) * 32);
            }
            unsigned a0 = *(const unsigned*)&sume[rA * pit + kt * 16 + cA];
            unsigned a1 = *(const unsigned*)&sume[(rA + 8) * pit + kt * 16 + cA];
            unsigned a2 = *(const unsigned*)&sume[rA * pit + kt * 16 + cA + 8];
            unsigned a3 = *(const unsigned*)&sume[(rA + 8) * pit + kt * 16 + cA + 8];
            #pragma unroll
            for (int g = 0; g < 4; g++) mma_bf16(c[g], a0, a1, a2, a3, bcur[g].x, bcur[g].y);
            #pragma unroll
            for (int g = 0; g < 4; g++) bcur[g] = bn[g];
        }
    }

    // only epilogue remains -> allow next step's prologue
    cudaTriggerProgrammaticLaunchCompletion();

    // ---------- register epilogue: c[g] = {i,f,o,g} gates of (rA,hb..hb+1),(rA+8,..) ----------
    if (is1 || !last) {
        float* cn = is1 ? g_c1[pout] : g_c0[pin];
        __nv_bfloat16* bo = is1 ? g_bh1[pout] : g_bh0[pin];
        #pragma unroll
        for (int p = 0; p < 2; p++) {
            int r = rA + p * 8;
            int grow = row0 + r;
            if (r < RPB && grow < NN) {
                float2 co = p ? cold1 : cold0;
                float i0 = c[0][2*p], i1 = c[0][2*p+1];
                float f0 = c[1][2*p], f1 = c[1][2*p+1];
                float o0 = c[2][2*p], o1 = c[2][2*p+1];
                float g0 = c[3][2*p], g1 = c[3][2*p+1];
                float cv0 = sigf(f0) * co.x + sigf(i0) * tanhf2(g0);
                float cv1 = sigf(f1) * co.y + sigf(i1) * tanhf2(g1);
                float h0 = sigf(o0) * tanhf2(cv0);
                float h1 = sigf(o1) * tanhf2(cv1);
                size_t gi = (size_t)grow * HH + hb;
                *(float2*)&cn[gi] = make_float2(cv0, cv1);
                __nv_bfloat162 hp = __floats2bfloat162_rn(h0, h1);
                *(__nv_bfloat162*)&bo[gi] = hp;
                if (is1 && last) *(float2*)&hl[r * HH + hb] = make_float2(h0, h1);
            }
        }
    }

    if (last) {
        // output projection from fp32 h1 staged in smem
        __syncthreads();
        if (tid < RPB * 12) {
            int r = tid / 12, p = tid - r * 12;
            int grow = row0 + r;
            if (grow < NN) {
                float s = outb[p];
                #pragma unroll
                for (int k = 0; k < HH; k++) s += hl[r * HH + k] * outW[k * 12 + p];
                out[grow * 12 + p] = s;
            }
        }
    }
}

extern "C" void kernel_launch(void* const* d_in, const int* in_sizes, int n_in,
                              void* d_out, int out_size) {
    const float* x     = (const float*)d_in[0];
    const float* adj   = (const float*)d_in[1];
    const float* gcWi0 = (const float*)d_in[2];
    const float* gcbi0 = (const float*)d_in[3];
    const float* gcWh0 = (const float*)d_in[4];
    const float* gcbh0 = (const float*)d_in[5];
    const float* liWi0 = (const float*)d_in[6];
    const float* libi0 = (const float*)d_in[7];
    const float* liWh0 = (const float*)d_in[8];
    const float* libh0 = (const float*)d_in[9];
    const float* gcWi1 = (const float*)d_in[10];
    const float* gcbi1 = (const float*)d_in[11];
    const float* gcWh1 = (const float*)d_in[12];
    const float* gcbh1 = (const float*)d_in[13];
    const float* liWi1 = (const float*)d_in[14];
    const float* libi1 = (const float*)d_in[15];
    const float* liWh1 = (const float*)d_in[16];
    const float* libh1 = (const float*)d_in[17];
    const float* outW  = (const float*)d_in[18];
    const float* outb  = (const float*)d_in[19];
    float* out = (float*)d_out;

    cudaFuncSetAttribute(k_cell0, cudaFuncAttributeMaxDynamicSharedMemorySize, C0_SMEM);
    cudaFuncSetAttribute(k_step, cudaFuncAttributeMaxDynamicSharedMemorySize, STEP_SMEM);

    k_dinv<<<NN / 8, 256>>>(adj);
    k_build<<<NN / 8, 256>>>(adj);
    k_prep<<<(PREP_TOTAL + 255) / 256, 256>>>(x,
        gcWi0, gcWh0, liWi0, liWh0, gcWi1, liWi1, gcWh1, liWh1,
        gcbi0, gcbh0, libi0, libh0, gcbi1, gcbh1, libi1, libh1);

    k_cell0<<<GRID, NTHR0, C0_SMEM>>>(x, 0, 0, 1);           // cell0 of step 0

    cudaLaunchConfig_t cfg = {};
    cfg.gridDim = dim3(GRID2, 1, 1);
    cfg.blockDim = dim3(512, 1, 1);
    cfg.dynamicSmemBytes = STEP_SMEM;
    cfg.stream = 0;
    cudaLaunchAttribute attrs[1];
    attrs[0].id = cudaLaunchAttributeProgrammaticStreamSerialization;
    attrs[0].val.programmaticStreamSerializationAllowed = 1;
    cfg.attrs = attrs;
    cfg.numAttrs = 1;
    for (int t = 0; t < TT; t++)
        cudaLaunchKernelEx(&cfg, k_step, x, outW, outb, out, t);  // cell1(t) + cell0(t+1)
}